// round 2
// baseline (speedup 1.0000x reference)
#include <cuda_runtime.h>

// Swin-style shifted window attention, fused single kernel.
// x[8,96,256,256] f32, WIN=8, SHIFT=4, HEADS=3, dh=32, L=64 tokens/window.
// One CTA per window (8192 CTAs), 256 threads, ~132KB dynamic smem.
// Rolls folded into gather/scatter index: read & write both at (coord+4)&255.

#define C        96
#define DH       32
#define L        64
#define NWS      32               // 256/8 windows per side
#define NWINDOWS (8 * NWS * NWS)  // 8192
#define LNS      100              // padded row stride (floats) for 64xC buffers
#define ATTS     68               // padded row stride for 64x64 attention tile

#define SMEM_FLOATS (4 * L * LNS + L * ATTS + 32 * LNS)
#define SMEM_BYTES  (SMEM_FLOATS * 4)

__global__ __launch_bounds__(256, 1)
void swin_fused_kernel(const float* __restrict__ x,
                       const float* __restrict__ ln_g, const float* __restrict__ ln_b,
                       const float* __restrict__ w_qkv, const float* __restrict__ b_qkv,
                       const float* __restrict__ w_out, const float* __restrict__ b_out,
                       const float* __restrict__ w_proj, const float* __restrict__ b_proj,
                       float* __restrict__ out)
{
    extern __shared__ float sm[];
    float* bufA = sm;                 // [64][LNS]: xw -> y -> attn output O
    float* bufQ = bufA + L * LNS;     // [64][LNS]: q (scaled) -> out-gemm result
    float* bufK = bufQ + L * LNS;     // [64][LNS]: k -> final proj result (staging)
    float* bufV = bufK + L * LNS;     // [64][LNS]: v
    float* att  = bufV + L * LNS;     // [64][ATTS]
    float* wt   = att  + L * ATTS;    // [32][LNS]: staged weight tile

    const int tid = threadIdx.x;
    const int wb  = blockIdx.x;
    const int b   = wb / (NWS * NWS);
    const int wi  = wb % (NWS * NWS);
    const int h0  = (wi / NWS) * 8;
    const int w0  = (wi % NWS) * 8;

    const int cg = tid & 31;   // col within 32-col tile
    const int tg = tid >> 5;   // token group (8 tokens each)

    // ---------------- Phase 0: gather window (roll folded in) ----------------
    for (int li = tid; li < L * C; li += 256) {
        int t = li & 63, c = li >> 6;
        int hh = (h0 + (t >> 3) + 4) & 255;
        int wc = (w0 + (t & 7) + 4) & 255;
        bufA[t * LNS + c] = x[((b * C + c) * 256 + hh) * 256 + wc];
    }
    __syncthreads();

    // ---------------- Phase 1: LayerNorm over C (4 lanes per token) ----------
    {
        int t = tid >> 2, s = tid & 3;
        float sum = 0.f, sq = 0.f;
        for (int c = s; c < C; c += 4) {
            float v = bufA[t * LNS + c];
            sum += v; sq += v * v;
        }
        sum += __shfl_xor_sync(0xffffffffu, sum, 1);
        sum += __shfl_xor_sync(0xffffffffu, sum, 2);
        sq  += __shfl_xor_sync(0xffffffffu, sq, 1);
        sq  += __shfl_xor_sync(0xffffffffu, sq, 2);
        float mu  = sum * (1.0f / C);
        float var = sq * (1.0f / C) - mu * mu;
        float rs  = rsqrtf(var + 1e-5f);
        for (int c = s; c < C; c += 4) {
            float v = bufA[t * LNS + c];
            bufA[t * LNS + c] = (v - mu) * rs * ln_g[c] + ln_b[c];
        }
    }
    __syncthreads();

    // ---------------- Phase 2: QKV GEMM  y[64,96] @ w_qkv^T[96,288] ----------
    const float qscale = 0.17677669529663687f;  // 1/sqrt(32)
    for (int ct = 0; ct < 9; ct++) {
        for (int li = tid; li < 32 * C; li += 256) {
            int r = li / C, k = li - r * C;
            wt[r * LNS + k] = w_qkv[(ct * 32 + r) * C + k];
        }
        __syncthreads();
        int col = ct * 32 + cg;
        float bias = b_qkv[col];
        float acc[8];
        #pragma unroll
        for (int r = 0; r < 8; r++) acc[r] = bias;
        #pragma unroll 6
        for (int k = 0; k < C; k += 4) {
            float4 wv = *(const float4*)&wt[cg * LNS + k];
            #pragma unroll
            for (int r = 0; r < 8; r++) {
                float4 yv = *(const float4*)&bufA[(tg * 8 + r) * LNS + k];
                acc[r] += yv.x * wv.x + yv.y * wv.y + yv.z * wv.z + yv.w * wv.w;
            }
        }
        float* dst; int dc; float mul;
        if (col < 96)       { dst = bufQ; dc = col;       mul = qscale; }
        else if (col < 192) { dst = bufK; dc = col - 96;  mul = 1.f; }
        else                { dst = bufV; dc = col - 192; mul = 1.f; }
        #pragma unroll
        for (int r = 0; r < 8; r++)
            dst[(tg * 8 + r) * LNS + dc] = acc[r] * mul;
        __syncthreads();
    }

    // ---------------- Phase 3: attention per head -----------------------------
    for (int hd = 0; hd < 3; hd++) {
        const int ho = hd * DH;
        // S = q_h @ k_h^T   (16x16 thread grid, 4x4 micro-tile)
        {
            int txx = tid & 15, tyy = tid >> 4;
            int i0 = tyy * 4, j0 = txx * 4;
            float acc[4][4] = {};
            #pragma unroll
            for (int d = 0; d < DH; d += 4) {
                float4 qv[4], kv[4];
                #pragma unroll
                for (int r = 0; r < 4; r++)
                    qv[r] = *(const float4*)&bufQ[(i0 + r) * LNS + ho + d];
                #pragma unroll
                for (int cc = 0; cc < 4; cc++)
                    kv[cc] = *(const float4*)&bufK[(j0 + cc) * LNS + ho + d];
                #pragma unroll
                for (int r = 0; r < 4; r++)
                    #pragma unroll
                    for (int cc = 0; cc < 4; cc++)
                        acc[r][cc] += qv[r].x * kv[cc].x + qv[r].y * kv[cc].y +
                                      qv[r].z * kv[cc].z + qv[r].w * kv[cc].w;
            }
            #pragma unroll
            for (int r = 0; r < 4; r++)
                #pragma unroll
                for (int cc = 0; cc < 4; cc++)
                    att[(i0 + r) * ATTS + j0 + cc] = acc[r][cc];
        }
        __syncthreads();
        // softmax over rows (4 lanes per row)
        {
            int t = tid >> 2, s = tid & 3;
            float mx = -1e30f;
            for (int j = s; j < L; j += 4) mx = fmaxf(mx, att[t * ATTS + j]);
            mx = fmaxf(mx, __shfl_xor_sync(0xffffffffu, mx, 1));
            mx = fmaxf(mx, __shfl_xor_sync(0xffffffffu, mx, 2));
            float sum = 0.f;
            for (int j = s; j < L; j += 4) {
                float p = __expf(att[t * ATTS + j] - mx);
                att[t * ATTS + j] = p;
                sum += p;
            }
            sum += __shfl_xor_sync(0xffffffffu, sum, 1);
            sum += __shfl_xor_sync(0xffffffffu, sum, 2);
            float inv = 1.0f / sum;
            for (int j = s; j < L; j += 4) att[t * ATTS + j] *= inv;
        }
        __syncthreads();
        // O_h = P @ v_h  (32 d-lanes x 8 token groups, 8 rows per thread)
        {
            int d = tid & 31, tg2 = tid >> 5;
            float acc[8] = {};
            #pragma unroll 4
            for (int m = 0; m < L; m += 4) {
                float v0 = bufV[(m + 0) * LNS + ho + d];
                float v1 = bufV[(m + 1) * LNS + ho + d];
                float v2 = bufV[(m + 2) * LNS + ho + d];
                float v3 = bufV[(m + 3) * LNS + ho + d];
                #pragma unroll
                for (int r = 0; r < 8; r++) {
                    float4 p = *(const float4*)&att[(tg2 * 8 + r) * ATTS + m];
                    acc[r] += p.x * v0 + p.y * v1 + p.z * v2 + p.w * v3;
                }
            }
            #pragma unroll
            for (int r = 0; r < 8; r++)
                bufA[(tg2 * 8 + r) * LNS + ho + d] = acc[r];
        }
        __syncthreads();
    }

    // ---------------- Phase 4: out GEMM  O @ w_out^T + b_out -> bufQ ---------
    for (int ct = 0; ct < 3; ct++) {
        for (int li = tid; li < 32 * C; li += 256) {
            int r = li / C, k = li - r * C;
            wt[r * LNS + k] = w_out[(ct * 32 + r) * C + k];
        }
        __syncthreads();
        int col = ct * 32 + cg;
        float acc[8];
        float bias = b_out[col];
        #pragma unroll
        for (int r = 0; r < 8; r++) acc[r] = bias;
        #pragma unroll 6
        for (int k = 0; k < C; k += 4) {
            float4 wv = *(const float4*)&wt[cg * LNS + k];
            #pragma unroll
            for (int r = 0; r < 8; r++) {
                float4 yv = *(const float4*)&bufA[(tg * 8 + r) * LNS + k];
                acc[r] += yv.x * wv.x + yv.y * wv.y + yv.z * wv.z + yv.w * wv.w;
            }
        }
        #pragma unroll
        for (int r = 0; r < 8; r++)
            bufQ[(tg * 8 + r) * LNS + col] = acc[r];
        __syncthreads();
    }

    // ---------------- Phase 5: proj GEMM  -> bufK, then scatter --------------
    for (int ct = 0; ct < 3; ct++) {
        for (int li = tid; li < 32 * C; li += 256) {
            int r = li / C, k = li - r * C;
            wt[r * LNS + k] = w_proj[(ct * 32 + r) * C + k];
        }
        __syncthreads();
        int col = ct * 32 + cg;
        float acc[8];
        float bias = b_proj[col];
        #pragma unroll
        for (int r = 0; r < 8; r++) acc[r] = bias;
        #pragma unroll 6
        for (int k = 0; k < C; k += 4) {
            float4 wv = *(const float4*)&wt[cg * LNS + k];
            #pragma unroll
            for (int r = 0; r < 8; r++) {
                float4 yv = *(const float4*)&bufQ[(tg * 8 + r) * LNS + k];
                acc[r] += yv.x * wv.x + yv.y * wv.y + yv.z * wv.z + yv.w * wv.w;
            }
        }
        #pragma unroll
        for (int r = 0; r < 8; r++)
            bufK[(tg * 8 + r) * LNS + col] = acc[r];
        __syncthreads();
    }

    // scatter back (roll folded in; same index as gather)
    for (int li = tid; li < L * C; li += 256) {
        int t = li & 63, c = li >> 6;
        int hh = (h0 + (t >> 3) + 4) & 255;
        int wc = (w0 + (t & 7) + 4) & 255;
        out[((b * C + c) * 256 + hh) * 256 + wc] = bufK[t * LNS + c];
    }
}

extern "C" void kernel_launch(void* const* d_in, const int* in_sizes, int n_in,
                              void* d_out, int out_size) {
    const float* x      = (const float*)d_in[0];
    const float* ln_g   = (const float*)d_in[1];
    const float* ln_b   = (const float*)d_in[2];
    const float* w_qkv  = (const float*)d_in[3];
    const float* b_qkv  = (const float*)d_in[4];
    const float* w_out  = (const float*)d_in[5];
    const float* b_out  = (const float*)d_in[6];
    const float* w_proj = (const float*)d_in[7];
    const float* b_proj = (const float*)d_in[8];
    float* out = (float*)d_out;

    cudaFuncSetAttribute(swin_fused_kernel,
                         cudaFuncAttributeMaxDynamicSharedMemorySize, SMEM_BYTES);
    swin_fused_kernel<<<NWINDOWS, 256, SMEM_BYTES>>>(
        x, ln_g, ln_b, w_qkv, b_qkv, w_out, b_out, w_proj, b_proj, out);
}